// round 1
// baseline (speedup 1.0000x reference)
#include <cuda_runtime.h>

#define BATCH 2
#define NUM_HEADS 16
#define D_K 128
#define NEW_LEN 2048
#define PAST_LEN 2048
#define D_MODEL 2048

// ---------------- scratch (static device globals; no allocation) ----------------
__device__ float g_Q [BATCH*NUM_HEADS*NEW_LEN*D_K];   // [b,h,s,d]
__device__ float g_Kn[BATCH*NUM_HEADS*NEW_LEN*D_K];   // new keys   [b,h,s,d]
__device__ float g_Vn[BATCH*NUM_HEADS*NEW_LEN*D_K];   // new values [b,h,s,d]
__device__ float g_attn[BATCH*NEW_LEN*D_MODEL];       // [b,s, h*128+d]

// =================================================================================
// SGEMM:  C[M,N] = A[M,K] @ B[N,K]^T   (both row-major; classic 128x128x8 tiling)
// mode 0: C row-major [M,N]
// mode 1: scatter to [b,h,s,d]: m=(b,s), n=(h,d)
// =================================================================================
__global__ __launch_bounds__(256)
void sgemm_abt(const float* __restrict__ A, const float* __restrict__ B,
               float* __restrict__ C, int K, int N, int mode)
{
    __shared__ float As[8][128];
    __shared__ float Bs[8][128];

    const int tid = threadIdx.x;
    const int m0 = blockIdx.y * 128;
    const int n0 = blockIdx.x * 128;
    const int ty = tid >> 4;        // 0..15
    const int tx = tid & 15;        // 0..15
    const int lrow = tid >> 1;      // 0..127
    const int lc   = (tid & 1) << 2;// 0 or 4

    float acc[8][8];
#pragma unroll
    for (int i = 0; i < 8; i++)
#pragma unroll
        for (int j = 0; j < 8; j++) acc[i][j] = 0.f;

    const float* Ap = A + (m0 + lrow) * K + lc;
    const float* Bp = B + (n0 + lrow) * K + lc;

    float4 av = *(const float4*)(Ap);
    float4 bv = *(const float4*)(Bp);

    for (int k0 = 0; k0 < K; k0 += 8) {
        __syncthreads();
        As[lc + 0][lrow] = av.x; As[lc + 1][lrow] = av.y;
        As[lc + 2][lrow] = av.z; As[lc + 3][lrow] = av.w;
        Bs[lc + 0][lrow] = bv.x; Bs[lc + 1][lrow] = bv.y;
        Bs[lc + 2][lrow] = bv.z; Bs[lc + 3][lrow] = bv.w;
        __syncthreads();

        if (k0 + 8 < K) {                      // prefetch next tile (overlaps FMAs)
            av = *(const float4*)(Ap + k0 + 8);
            bv = *(const float4*)(Bp + k0 + 8);
        }

#pragma unroll
        for (int kk = 0; kk < 8; kk++) {
            float4 a0 = *(float4*)&As[kk][ty * 8];
            float4 a1 = *(float4*)&As[kk][ty * 8 + 4];
            float4 b0 = *(float4*)&Bs[kk][tx * 8];
            float4 b1 = *(float4*)&Bs[kk][tx * 8 + 4];
            float a[8] = {a0.x,a0.y,a0.z,a0.w,a1.x,a1.y,a1.z,a1.w};
            float bb[8]= {b0.x,b0.y,b0.z,b0.w,b1.x,b1.y,b1.z,b1.w};
#pragma unroll
            for (int i = 0; i < 8; i++)
#pragma unroll
                for (int j = 0; j < 8; j++)
                    acc[i][j] += a[i] * bb[j];
        }
    }

    // epilogue
#pragma unroll
    for (int i = 0; i < 8; i++) {
        const int m = m0 + ty * 8 + i;
#pragma unroll
        for (int j4 = 0; j4 < 8; j4 += 4) {
            const int n = n0 + tx * 8 + j4;
            float4 v = make_float4(acc[i][j4], acc[i][j4+1], acc[i][j4+2], acc[i][j4+3]);
            if (mode == 0) {
                *(float4*)&C[m * N + n] = v;
            } else {
                const int b = m >> 11, s = m & 2047;
                const int h = n >> 7,  d = n & 127;
                *(float4*)&C[((b * NUM_HEADS + h) * NEW_LEN + s) * D_K + d] = v;
            }
        }
    }
}

// =================================================================================
// Flash attention: per block = (q-tile of 64, head, batch). d_k = 128 resident.
// smem: Qs 64x132, KVs 64x132 (K then V reuse), Pt 64x68 (P transposed)
// threads 256 = 16x16; S microtile 4x4; O microtile 4 rows x 8 cols
// =================================================================================
#define ATT_SMEM_FLOATS (2*64*132 + 64*68)

__global__ __launch_bounds__(256)
void attn_kernel(const float* __restrict__ past_k, const float* __restrict__ past_v)
{
    extern __shared__ float sm[];
    float* Qs  = sm;                 // [64][132]
    float* KVs = sm + 64 * 132;      // [64][132]
    float* Pt  = sm + 2 * 64 * 132;  // [64][68]  Pt[j][r]

    const int tid = threadIdx.x;
    const int ty = tid >> 4;   // 0..15 -> rows 4ty..4ty+3
    const int tx = tid & 15;   // 0..15 -> S cols 4tx..; O cols 8tx..
    const int qt = blockIdx.x;
    const int h  = blockIdx.y;
    const int b  = blockIdx.z;

    const float SCALE = 0.08838834764831845f;  // 1/sqrt(128)

    // ---- load Q tile (scaled) ----
    const float* Qg = g_Q + ((b * NUM_HEADS + h) * NEW_LEN + qt * 64) * D_K;
    for (int i = tid; i < 64 * 32; i += 256) {
        int r = i >> 5, c = (i & 31) << 2;
        float4 v = *(const float4*)&Qg[r * 128 + c];
        v.x *= SCALE; v.y *= SCALE; v.z *= SCALE; v.w *= SCALE;
        *(float4*)&Qs[r * 132 + c] = v;
    }

    float m_i[4], l_i[4], O[4][8];
#pragma unroll
    for (int i = 0; i < 4; i++) {
        m_i[i] = -1e30f; l_i[i] = 0.f;
#pragma unroll
        for (int c = 0; c < 8; c++) O[i][c] = 0.f;
    }

    const int ntiles = PAST_LEN / 64 + qt + 1;  // causal: up to diagonal tile
    const int bh = b * NUM_HEADS + h;

    for (int kt = 0; kt < ntiles; kt++) {
        const bool diag = (kt == ntiles - 1);
        const float* Kg = (kt < PAST_LEN / 64)
            ? past_k + (bh * PAST_LEN + kt * 64) * D_K
            : g_Kn   + (bh * NEW_LEN  + (kt - PAST_LEN / 64) * 64) * D_K;
        const float* Vg = (kt < PAST_LEN / 64)
            ? past_v + (bh * PAST_LEN + kt * 64) * D_K
            : g_Vn   + (bh * NEW_LEN  + (kt - PAST_LEN / 64) * 64) * D_K;

        __syncthreads();   // prev PV done reading KVs/Pt, Qs load done (first iter)
        for (int i = tid; i < 64 * 32; i += 256) {
            int r = i >> 5, c = (i & 31) << 2;
            *(float4*)&KVs[r * 132 + c] = *(const float4*)&Kg[r * 128 + c];
        }
        __syncthreads();

        // ---- S = Q K^T (4x4 per thread) ----
        float s[4][4];
#pragma unroll
        for (int i = 0; i < 4; i++)
#pragma unroll
            for (int j = 0; j < 4; j++) s[i][j] = 0.f;

#pragma unroll 4
        for (int d0 = 0; d0 < 128; d0 += 4) {
            float4 q[4], k[4];
#pragma unroll
            for (int i = 0; i < 4; i++) q[i] = *(float4*)&Qs[(ty * 4 + i) * 132 + d0];
#pragma unroll
            for (int j = 0; j < 4; j++) k[j] = *(float4*)&KVs[(tx * 4 + j) * 132 + d0];
#pragma unroll
            for (int i = 0; i < 4; i++)
#pragma unroll
                for (int j = 0; j < 4; j++) {
                    s[i][j] += q[i].x * k[j].x;
                    s[i][j] += q[i].y * k[j].y;
                    s[i][j] += q[i].z * k[j].z;
                    s[i][j] += q[i].w * k[j].w;
                }
        }

        if (diag) {
#pragma unroll
            for (int i = 0; i < 4; i++)
#pragma unroll
                for (int j = 0; j < 4; j++)
                    if (tx * 4 + j > ty * 4 + i) s[i][j] = -1e30f;
        }

        // ---- online softmax (row stats across the 16 tx-lanes) ----
#pragma unroll
        for (int i = 0; i < 4; i++) {
            float mx = fmaxf(fmaxf(s[i][0], s[i][1]), fmaxf(s[i][2], s[i][3]));
#pragma unroll
            for (int o = 8; o; o >>= 1) mx = fmaxf(mx, __shfl_xor_sync(0xffffffffu, mx, o));
            const float mnew = fmaxf(m_i[i], mx);
            const float alpha = __expf(m_i[i] - mnew);
            m_i[i] = mnew;
            float rs = 0.f;
#pragma unroll
            for (int j = 0; j < 4; j++) {
                float p = __expf(s[i][j] - mnew);
                s[i][j] = p; rs += p;
            }
#pragma unroll
            for (int o = 8; o; o >>= 1) rs += __shfl_xor_sync(0xffffffffu, rs, o);
            l_i[i] = l_i[i] * alpha + rs;
#pragma unroll
            for (int c = 0; c < 8; c++) O[i][c] *= alpha;
#pragma unroll
            for (int j = 0; j < 4; j++)
                Pt[(tx * 4 + j) * 68 + ty * 4 + i] = s[i][j];
        }

        __syncthreads();   // Pt written; S-phase done reading KVs
        for (int i = tid; i < 64 * 32; i += 256) {
            int r = i >> 5, c = (i & 31) << 2;
            *(float4*)&KVs[r * 132 + c] = *(const float4*)&Vg[r * 128 + c];
        }
        __syncthreads();

        // ---- O += P V (4 rows x 8 cols per thread) ----
#pragma unroll 4
        for (int j = 0; j < 64; j++) {
            float4 p4 = *(float4*)&Pt[j * 68 + ty * 4];
            float4 v0 = *(float4*)&KVs[j * 132 + tx * 8];
            float4 v1 = *(float4*)&KVs[j * 132 + tx * 8 + 4];
            float pv[4] = {p4.x, p4.y, p4.z, p4.w};
#pragma unroll
            for (int i = 0; i < 4; i++) {
                O[i][0] += pv[i] * v0.x; O[i][1] += pv[i] * v0.y;
                O[i][2] += pv[i] * v0.z; O[i][3] += pv[i] * v0.w;
                O[i][4] += pv[i] * v1.x; O[i][5] += pv[i] * v1.y;
                O[i][6] += pv[i] * v1.z; O[i][7] += pv[i] * v1.w;
            }
        }
    }

    // ---- epilogue: normalize, write [b, s, h*128 + c] ----
    float* Og = g_attn + (b * NEW_LEN + qt * 64) * D_MODEL + h * D_K;
#pragma unroll
    for (int i = 0; i < 4; i++) {
        const float inv = 1.f / l_i[i];
        const int r = ty * 4 + i;
        float4 o0 = make_float4(O[i][0]*inv, O[i][1]*inv, O[i][2]*inv, O[i][3]*inv);
        float4 o1 = make_float4(O[i][4]*inv, O[i][5]*inv, O[i][6]*inv, O[i][7]*inv);
        *(float4*)&Og[r * D_MODEL + tx * 8]     = o0;
        *(float4*)&Og[r * D_MODEL + tx * 8 + 4] = o1;
    }
}

// =================================================================================
extern "C" void kernel_launch(void* const* d_in, const int* in_sizes, int n_in,
                              void* d_out, int out_size)
{
    (void)in_sizes; (void)n_in; (void)out_size;
    const float* x      = (const float*)d_in[0];
    const float* past_k = (const float*)d_in[1];
    const float* past_v = (const float*)d_in[2];
    const float* Wq     = (const float*)d_in[3];
    const float* Wk     = (const float*)d_in[4];
    const float* Wv     = (const float*)d_in[5];
    const float* Wo     = (const float*)d_in[6];
    float* out = (float*)d_out;

    float *qp, *kp, *vp, *ap;
    cudaGetSymbolAddress((void**)&qp, g_Q);
    cudaGetSymbolAddress((void**)&kp, g_Kn);
    cudaGetSymbolAddress((void**)&vp, g_Vn);
    cudaGetSymbolAddress((void**)&ap, g_attn);

    dim3 gproj(D_MODEL / 128, (BATCH * NEW_LEN) / 128);

    // Q/K/V projections (scatter to [b,h,s,d])
    sgemm_abt<<<gproj, 256>>>(x, Wq, qp, D_MODEL, D_MODEL, 1);
    sgemm_abt<<<gproj, 256>>>(x, Wk, kp, D_MODEL, D_MODEL, 1);
    sgemm_abt<<<gproj, 256>>>(x, Wv, vp, D_MODEL, D_MODEL, 1);

    // flash attention
    const int smem_bytes = ATT_SMEM_FLOATS * (int)sizeof(float);
    cudaFuncSetAttribute(attn_kernel, cudaFuncAttributeMaxDynamicSharedMemorySize, smem_bytes);
    attn_kernel<<<dim3(NEW_LEN / 64, NUM_HEADS, BATCH), 256, smem_bytes>>>(past_k, past_v);

    // output projection
    sgemm_abt<<<gproj, 256>>>(ap, Wo, out, D_MODEL, D_MODEL, 0);
}

// round 2
// speedup vs baseline: 4.0262x; 4.0262x over previous
#include <cuda_runtime.h>
#include <cstdint>

#define BATCH 2
#define NUM_HEADS 16
#define D_K 128
#define NEW_LEN 2048
#define PAST_LEN 2048
#define D_MODEL 2048

// ---------------- scratch (static device globals; no allocation) ----------------
__device__ float g_Q [BATCH*NUM_HEADS*NEW_LEN*D_K];   // [b,h,s,d]
__device__ float g_Kn[BATCH*NUM_HEADS*NEW_LEN*D_K];   // new keys   [b,h,s,d]
__device__ float g_Vn[BATCH*NUM_HEADS*NEW_LEN*D_K];   // new values [b,h,s,d]
__device__ float g_attn[BATCH*NEW_LEN*D_MODEL];       // [b,s, h*128+d]

// ---------------- tf32 helpers ----------------
__device__ __forceinline__ uint32_t f2t(float x) {
    uint32_t u;
    asm("cvt.rna.tf32.f32 %0, %1;" : "=r"(u) : "f"(x));
    return u;
}

__device__ __forceinline__ void mma8(float* c, const uint32_t* a, uint32_t b0, uint32_t b1) {
    asm volatile(
        "mma.sync.aligned.m16n8k8.row.col.f32.tf32.tf32.f32 "
        "{%0,%1,%2,%3},{%4,%5,%6,%7},{%8,%9},{%0,%1,%2,%3};"
        : "+f"(c[0]), "+f"(c[1]), "+f"(c[2]), "+f"(c[3])
        : "r"(a[0]), "r"(a[1]), "r"(a[2]), "r"(a[3]), "r"(b0), "r"(b1));
}

// =================================================================================
// TF32 GEMM:  C[M,N] = A[M,K] @ B[N,K]^T  (both row-major)
// block 128x128, Ktile 32, 256 threads = 8 warps, warp tile 64x32
// smem [row][k] with ld=36 (stride == 4 mod 32 banks -> conflict-free frag loads)
// mode 0: C row-major [M,N];  mode 1: scatter to [b,h,s,d]
// =================================================================================
#define GLD 36

__global__ __launch_bounds__(256)
void sgemm_tf32(const float* __restrict__ A, const float* __restrict__ B,
                float* __restrict__ C, int K, int N, int mode)
{
    __shared__ uint32_t As[128 * GLD];
    __shared__ uint32_t Bs[128 * GLD];

    const int tid  = threadIdx.x;
    const int lane = tid & 31;
    const int warp = tid >> 5;
    const int lr = lane >> 2;   // 0..7
    const int lc = lane & 3;    // 0..3

    const int m0 = blockIdx.y * 128;
    const int n0 = blockIdx.x * 128;
    const int wm = (warp & 1) * 64;
    const int wn = (warp >> 1) * 32;

    // global staging: thread -> row tm (4 passes of 32 rows), 1 float4 at col tk
    const int tm = tid >> 3;          // 0..31
    const int tk = (tid & 7) * 4;     // 0,4,..,28

    const float* Ag = A + (size_t)(m0 + tm) * K + tk;
    const float* Bg = B + (size_t)(n0 + tm) * K + tk;

    float acc[4][4][4];
#pragma unroll
    for (int mt = 0; mt < 4; mt++)
#pragma unroll
        for (int nt = 0; nt < 4; nt++)
#pragma unroll
            for (int i = 0; i < 4; i++) acc[mt][nt][i] = 0.f;

    float4 pa[4], pb[4];
#pragma unroll
    for (int i = 0; i < 4; i++) {
        pa[i] = *(const float4*)(Ag + (size_t)i * 32 * K);
        pb[i] = *(const float4*)(Bg + (size_t)i * 32 * K);
    }

    for (int k0 = 0; k0 < K; k0 += 32) {
        __syncthreads();
#pragma unroll
        for (int i = 0; i < 4; i++) {
            uint4 ua = make_uint4(f2t(pa[i].x), f2t(pa[i].y), f2t(pa[i].z), f2t(pa[i].w));
            uint4 ub = make_uint4(f2t(pb[i].x), f2t(pb[i].y), f2t(pb[i].z), f2t(pb[i].w));
            *(uint4*)&As[(tm + 32 * i) * GLD + tk] = ua;
            *(uint4*)&Bs[(tm + 32 * i) * GLD + tk] = ub;
        }
        __syncthreads();

        if (k0 + 32 < K) {
#pragma unroll
            for (int i = 0; i < 4; i++) {
                pa[i] = *(const float4*)(Ag + (size_t)i * 32 * K + k0 + 32);
                pb[i] = *(const float4*)(Bg + (size_t)i * 32 * K + k0 + 32);
            }
        }

#pragma unroll
        for (int ks = 0; ks < 4; ks++) {
            const int k = ks * 8;
            uint32_t a[4][4];
            uint32_t b[4][2];
#pragma unroll
            for (int mt = 0; mt < 4; mt++) {
                const int r = wm + mt * 16 + lr;
                a[mt][0] = As[r * GLD + k + lc];
                a[mt][1] = As[(r + 8) * GLD + k + lc];
                a[mt][2] = As[r * GLD + k + lc + 4];
                a[mt][3] = As[(r + 8) * GLD + k + lc + 4];
            }
#pragma unroll
            for (int nt = 0; nt < 4; nt++) {
                const int r = wn + nt * 8 + lr;
                b[nt][0] = Bs[r * GLD + k + lc];
                b[nt][1] = Bs[r * GLD + k + lc + 4];
            }
#pragma unroll
            for (int mt = 0; mt < 4; mt++)
#pragma unroll
                for (int nt = 0; nt < 4; nt++)
                    mma8(acc[mt][nt], a[mt], b[nt][0], b[nt][1]);
        }
    }

    // epilogue
#pragma unroll
    for (int mt = 0; mt < 4; mt++) {
#pragma unroll
        for (int nt = 0; nt < 4; nt++) {
            const int row0 = m0 + wm + mt * 16 + lr;
            const int row1 = row0 + 8;
            const int col  = n0 + wn + nt * 8 + 2 * lc;
            float2 v0 = make_float2(acc[mt][nt][0], acc[mt][nt][1]);
            float2 v1 = make_float2(acc[mt][nt][2], acc[mt][nt][3]);
            if (mode == 0) {
                *(float2*)&C[(size_t)row0 * N + col] = v0;
                *(float2*)&C[(size_t)row1 * N + col] = v1;
            } else {
                const int h = col >> 7, d = col & 127;
                const int b0_ = row0 >> 11, s0 = row0 & 2047;
                const int b1_ = row1 >> 11, s1 = row1 & 2047;
                *(float2*)&C[(((size_t)b0_ * NUM_HEADS + h) * NEW_LEN + s0) * D_K + d] = v0;
                *(float2*)&C[(((size_t)b1_ * NUM_HEADS + h) * NEW_LEN + s1) * D_K + d] = v1;
            }
        }
    }
}

// =================================================================================
// TF32 flash attention: block = (64 q-rows, head, batch), 128 threads = 4 warps,
// each warp owns 16 q-rows. Q lives in A-fragments in registers for the whole
// kernel. K tile smem ld=132 (==4 mod 32 banks, 8row x 4col frag loads);
// V tile ld=136 (==8 mod 32, 4row x 8col frag loads); P per-warp smem ld=68.
// =================================================================================
#define KLD 132
#define VLD 136
#define PLD 68
#define ATT_SMEM_U32 (64 * VLD + 64 * PLD)   // 8704 + 4352 = 13056 u32 = 52224 B

__global__ __launch_bounds__(128)
void attn_mma(const float* __restrict__ past_k, const float* __restrict__ past_v)
{
    extern __shared__ uint32_t sm[];
    uint32_t* KV = sm;              // K with ld=KLD, V with ld=VLD (reused)
    uint32_t* Ps = sm + 64 * VLD;   // [64][PLD]

    const int tid  = threadIdx.x;
    const int lane = tid & 31;
    const int w    = tid >> 5;
    const int lr = lane >> 2;   // 0..7
    const int lc = lane & 3;    // 0..3

    const int qt = blockIdx.x;
    const int h  = blockIdx.y;
    const int b  = blockIdx.z;
    const int bh = b * NUM_HEADS + h;

    const float SCALE = 0.08838834764831845f;  // 1/sqrt(128)

    // ---- stage Q tile (scaled, tf32) into KV, then read into A-fragments ----
    const float* Qg = g_Q + (((size_t)bh) * NEW_LEN + qt * 64) * D_K;
    for (int i = tid; i < 64 * 32; i += 128) {
        const int r = i >> 5, c = (i & 31) << 2;
        float4 v = *(const float4*)&Qg[r * 128 + c];
        KV[r * KLD + c + 0] = f2t(v.x * SCALE);
        KV[r * KLD + c + 1] = f2t(v.y * SCALE);
        KV[r * KLD + c + 2] = f2t(v.z * SCALE);
        KV[r * KLD + c + 3] = f2t(v.w * SCALE);
    }
    __syncthreads();

    uint32_t q[16][4];
    {
        const int r0 = w * 16 + lr;
#pragma unroll
        for (int ks = 0; ks < 16; ks++) {
            const int k = ks * 8;
            q[ks][0] = KV[r0 * KLD + k + lc];
            q[ks][1] = KV[(r0 + 8) * KLD + k + lc];
            q[ks][2] = KV[r0 * KLD + k + lc + 4];
            q[ks][3] = KV[(r0 + 8) * KLD + k + lc + 4];
        }
    }

    float o[16][4];
#pragma unroll
    for (int nt = 0; nt < 16; nt++)
#pragma unroll
        for (int i = 0; i < 4; i++) o[nt][i] = 0.f;
    float m0 = -1e30f, m1 = -1e30f, l0 = 0.f, l1 = 0.f;

    const int ntiles = PAST_LEN / 64 + qt + 1;

    for (int kt = 0; kt < ntiles; kt++) {
        const bool diag = (kt == ntiles - 1);
        const float* Kg = (kt < PAST_LEN / 64)
            ? past_k + (((size_t)bh) * PAST_LEN + kt * 64) * D_K
            : g_Kn   + (((size_t)bh) * NEW_LEN + (kt - PAST_LEN / 64) * 64) * D_K;
        const float* Vg = (kt < PAST_LEN / 64)
            ? past_v + (((size_t)bh) * PAST_LEN + kt * 64) * D_K
            : g_Vn   + (((size_t)bh) * NEW_LEN + (kt - PAST_LEN / 64) * 64) * D_K;

        __syncthreads();   // prior V reads (or q-frag reads) complete
        for (int i = tid; i < 64 * 32; i += 128) {
            const int r = i >> 5, c = (i & 31) << 2;
            float4 v = *(const float4*)&Kg[r * 128 + c];
            KV[r * KLD + c + 0] = f2t(v.x);
            KV[r * KLD + c + 1] = f2t(v.y);
            KV[r * KLD + c + 2] = f2t(v.z);
            KV[r * KLD + c + 3] = f2t(v.w);
        }
        __syncthreads();

        // ---- S = Q K^T : 8 n-tiles of 16x8 per warp ----
        float sc[8][4];
#pragma unroll
        for (int nt = 0; nt < 8; nt++)
#pragma unroll
            for (int i = 0; i < 4; i++) sc[nt][i] = 0.f;

#pragma unroll
        for (int ks = 0; ks < 16; ks++) {
            const int k = ks * 8;
#pragma unroll
            for (int nt = 0; nt < 8; nt++) {
                const uint32_t b0 = KV[(nt * 8 + lr) * KLD + k + lc];
                const uint32_t b1 = KV[(nt * 8 + lr) * KLD + k + lc + 4];
                mma8(sc[nt], q[ks], b0, b1);
            }
        }

        if (diag) {
            const int r0 = w * 16 + lr;
#pragma unroll
            for (int nt = 0; nt < 8; nt++) {
                const int c0 = nt * 8 + 2 * lc;
                if (c0     > r0    ) sc[nt][0] = -1e30f;
                if (c0 + 1 > r0    ) sc[nt][1] = -1e30f;
                if (c0     > r0 + 8) sc[nt][2] = -1e30f;
                if (c0 + 1 > r0 + 8) sc[nt][3] = -1e30f;
            }
        }

        // ---- online softmax: rows (w*16+lr) and (+8); stats over 4 lanes ----
        float mx0 = -1e30f, mx1 = -1e30f;
#pragma unroll
        for (int nt = 0; nt < 8; nt++) {
            mx0 = fmaxf(mx0, fmaxf(sc[nt][0], sc[nt][1]));
            mx1 = fmaxf(mx1, fmaxf(sc[nt][2], sc[nt][3]));
        }
        mx0 = fmaxf(mx0, __shfl_xor_sync(0xffffffffu, mx0, 1));
        mx0 = fmaxf(mx0, __shfl_xor_sync(0xffffffffu, mx0, 2));
        mx1 = fmaxf(mx1, __shfl_xor_sync(0xffffffffu, mx1, 1));
        mx1 = fmaxf(mx1, __shfl_xor_sync(0xffffffffu, mx1, 2));

        const float mn0 = fmaxf(m0, mx0);
        const float mn1 = fmaxf(m1, mx1);
        const float al0 = __expf(m0 - mn0);
        const float al1 = __expf(m1 - mn1);
        m0 = mn0; m1 = mn1;

        float s0 = 0.f, s1 = 0.f;
#pragma unroll
        for (int nt = 0; nt < 8; nt++) {
            float p0 = __expf(sc[nt][0] - mn0);
            float p1 = __expf(sc[nt][1] - mn0);
            float p2 = __expf(sc[nt][2] - mn1);
            float p3 = __expf(sc[nt][3] - mn1);
            s0 += p0 + p1; s1 += p2 + p3;
            sc[nt][0] = p0; sc[nt][1] = p1; sc[nt][2] = p2; sc[nt][3] = p3;
        }
        s0 += __shfl_xor_sync(0xffffffffu, s0, 1);
        s0 += __shfl_xor_sync(0xffffffffu, s0, 2);
        s1 += __shfl_xor_sync(0xffffffffu, s1, 1);
        s1 += __shfl_xor_sync(0xffffffffu, s1, 2);
        l0 = l0 * al0 + s0;
        l1 = l1 * al1 + s1;

#pragma unroll
        for (int nt = 0; nt < 16; nt++) {
            o[nt][0] *= al0; o[nt][1] *= al0;
            o[nt][2] *= al1; o[nt][3] *= al1;
        }

        // P -> per-warp-private smem rows (tf32)
        {
            const int r0 = w * 16 + lr;
#pragma unroll
            for (int nt = 0; nt < 8; nt++) {
                const int c0 = nt * 8 + 2 * lc;
                Ps[r0 * PLD + c0]           = f2t(sc[nt][0]);
                Ps[r0 * PLD + c0 + 1]       = f2t(sc[nt][1]);
                Ps[(r0 + 8) * PLD + c0]     = f2t(sc[nt][2]);
                Ps[(r0 + 8) * PLD + c0 + 1] = f2t(sc[nt][3]);
            }
        }

        __syncthreads();   // all warps done reading K
        for (int i = tid; i < 64 * 32; i += 128) {
            const int r = i >> 5, c = (i & 31) << 2;
            float4 v = *(const float4*)&Vg[r * 128 + c];
            KV[r * VLD + c + 0] = f2t(v.x);
            KV[r * VLD + c + 1] = f2t(v.y);
            KV[r * VLD + c + 2] = f2t(v.z);
            KV[r * VLD + c + 3] = f2t(v.w);
        }
        __syncthreads();

        // ---- O += P V : 16 n-tiles of 16x8 per warp, k = 64 ----
        const int r0 = w * 16 + lr;
#pragma unroll
        for (int kk = 0; kk < 8; kk++) {
            const int k = kk * 8;
            uint32_t a[4];
            a[0] = Ps[r0 * PLD + k + lc];
            a[1] = Ps[(r0 + 8) * PLD + k + lc];
            a[2] = Ps[r0 * PLD + k + lc + 4];
            a[3] = Ps[(r0 + 8) * PLD + k + lc + 4];
#pragma unroll
            for (int nt = 0; nt < 16; nt++) {
                const uint32_t b0 = KV[(k + lc) * VLD + nt * 8 + lr];
                const uint32_t b1 = KV[(k + lc + 4) * VLD + nt * 8 + lr];
                mma8(o[nt], a, b0, b1);
            }
        }
    }

    // ---- epilogue: normalize and write [b, s, h*128 + d] ----
    const float inv0 = 1.f / l0;
    const float inv1 = 1.f / l1;
    const int s0 = qt * 64 + w * 16 + lr;
    const int s1 = s0 + 8;
    float* O0 = g_attn + ((size_t)b * NEW_LEN + s0) * D_MODEL + h * D_K;
    float* O1 = g_attn + ((size_t)b * NEW_LEN + s1) * D_MODEL + h * D_K;
#pragma unroll
    for (int nt = 0; nt < 16; nt++) {
        const int d = nt * 8 + 2 * lc;
        *(float2*)&O0[d] = make_float2(o[nt][0] * inv0, o[nt][1] * inv0);
        *(float2*)&O1[d] = make_float2(o[nt][2] * inv1, o[nt][3] * inv1);
    }
}

// =================================================================================
extern "C" void kernel_launch(void* const* d_in, const int* in_sizes, int n_in,
                              void* d_out, int out_size)
{
    (void)in_sizes; (void)n_in; (void)out_size;
    const float* x      = (const float*)d_in[0];
    const float* past_k = (const float*)d_in[1];
    const float* past_v = (const float*)d_in[2];
    const float* Wq     = (const float*)d_in[3];
    const float* Wk     = (const float*)d_in[4];
    const float* Wv     = (const float*)d_in[5];
    const float* Wo     = (const float*)d_in[6];
    float* out = (float*)d_out;

    float *qp, *kp, *vp, *ap;
    cudaGetSymbolAddress((void**)&qp, g_Q);
    cudaGetSymbolAddress((void**)&kp, g_Kn);
    cudaGetSymbolAddress((void**)&vp, g_Vn);
    cudaGetSymbolAddress((void**)&ap, g_attn);

    dim3 gproj(D_MODEL / 128, (BATCH * NEW_LEN) / 128);

    sgemm_tf32<<<gproj, 256>>>(x, Wq, qp, D_MODEL, D_MODEL, 1);
    sgemm_tf32<<<gproj, 256>>>(x, Wk, kp, D_MODEL, D_MODEL, 1);
    sgemm_tf32<<<gproj, 256>>>(x, Wv, vp, D_MODEL, D_MODEL, 1);

    const int smem_bytes = ATT_SMEM_U32 * (int)sizeof(uint32_t);
    cudaFuncSetAttribute(attn_mma, cudaFuncAttributeMaxDynamicSharedMemorySize, smem_bytes);
    attn_mma<<<dim3(NEW_LEN / 64, NUM_HEADS, BATCH), 128, smem_bytes>>>(past_k, past_v);

    sgemm_tf32<<<gproj, 256>>>(ap, Wo, out, D_MODEL, D_MODEL, 0);
}